// round 3
// baseline (speedup 1.0000x reference)
#include <cuda_runtime.h>
#include <cuda_bf16.h>
#include <math.h>

#define N_TOK   4096
#define DIM     1024
#define NHEAD   16
#define HDIM    64

// ---------------------------------------------------------------------------
// Scratch (static device globals — no runtime allocation)
// ---------------------------------------------------------------------------
__device__ float g_q[N_TOK * DIM];
__device__ float g_k[N_TOK * DIM];
__device__ float g_v[N_TOK * DIM];
__device__ float g_attn[N_TOK * DIM];

// ---------------------------------------------------------------------------
// GEMM: Y[M,1024] = X[M,1024] @ W[1024,1024]^T + b
// Both X rows and W rows are contiguous along the reduction dim (NT gemm).
// 64x64 block tile, 4x4 per-thread microtile, BK=16, 256 threads.
// Static smem: 2 * 64*17*4 * ... = 33,280 B < 48 KB.
// ---------------------------------------------------------------------------
__global__ __launch_bounds__(256)
void gemm_bias_kernel(const float* __restrict__ X,
                      const float* __restrict__ W,
                      const float* __restrict__ bias,
                      float* __restrict__ Y)
{
    __shared__ float Xs[64][17];   // [m][k], pad to 17 floats
    __shared__ float Ws[64][17];   // [n][k]

    const int tx = threadIdx.x;          // 0..15 -> output col group
    const int ty = threadIdx.y;          // 0..15 -> output row group
    const int tid = ty * 16 + tx;

    const int bm = blockIdx.y * 64;
    const int bn = blockIdx.x * 64;

    // loader mapping: each thread loads one float4 of each tile per k-step
    const int lr = tid >> 2;             // 0..63
    const int lc = (tid & 3) * 4;        // 0,4,8,12

    float acc[4][4] = {};

    const float* xrow = X + (size_t)(bm + lr) * DIM;
    const float* wrow = W + (size_t)(bn + lr) * DIM;

    for (int k0 = 0; k0 < DIM; k0 += 16) {
        float4 xv = *(const float4*)(xrow + k0 + lc);
        float4 wv = *(const float4*)(wrow + k0 + lc);
        Xs[lr][lc + 0] = xv.x; Xs[lr][lc + 1] = xv.y;
        Xs[lr][lc + 2] = xv.z; Xs[lr][lc + 3] = xv.w;
        Ws[lr][lc + 0] = wv.x; Ws[lr][lc + 1] = wv.y;
        Ws[lr][lc + 2] = wv.z; Ws[lr][lc + 3] = wv.w;
        __syncthreads();

        #pragma unroll
        for (int k = 0; k < 16; ++k) {
            float a[4], b[4];
            #pragma unroll
            for (int i = 0; i < 4; ++i) a[i] = Xs[ty * 4 + i][k];
            #pragma unroll
            for (int j = 0; j < 4; ++j) b[j] = Ws[tx * 4 + j][k];
            #pragma unroll
            for (int i = 0; i < 4; ++i)
                #pragma unroll
                for (int j = 0; j < 4; ++j)
                    acc[i][j] = fmaf(a[i], b[j], acc[i][j]);
        }
        __syncthreads();
    }

    #pragma unroll
    for (int i = 0; i < 4; ++i) {
        float* yrow = Y + (size_t)(bm + ty * 4 + i) * DIM + bn;
        #pragma unroll
        for (int j = 0; j < 4; ++j)
            yrow[tx * 4 + j] = acc[i][j] + bias[bn + tx * 4 + j];
    }
}

// ---------------------------------------------------------------------------
// Flash attention (fp32, online softmax).
// Block: 64 query rows of one head. 256 threads (16x16), 4x4 microtiles.
// Iterates over all 4096 keys in 64-wide tiles.
// Q/K/V stored [N, 1024]; head h occupies cols h*64 .. h*64+63.
// Dynamic smem: 3 tiles of 64x65 floats = 49,920 B (needs opt-in attribute).
// ---------------------------------------------------------------------------
#define TPAD 65
#define ATTN_SMEM_BYTES (3 * 64 * TPAD * 4)

__global__ __launch_bounds__(256)
void attn_kernel(const float* __restrict__ Q,
                 const float* __restrict__ K,
                 const float* __restrict__ V,
                 float* __restrict__ O)
{
    extern __shared__ float smem[];
    float* Qs  = smem;                    // [64][TPAD]
    float* KVs = smem + 64 * TPAD;        // [64][TPAD]  (K tile, then V tile)
    float* Ps  = smem + 2 * 64 * TPAD;    // [64][TPAD]

    const int tx = threadIdx.x;
    const int ty = threadIdx.y;
    const int tid = ty * 16 + tx;

    const int n0   = blockIdx.x * 64;   // query row tile
    const int head = blockIdx.y;
    const int base = head * HDIM;       // column offset of this head

    // loader mapping: 64 rows x 64 cols = 4096 floats, 16 per thread
    const int lr = tid >> 2;            // 0..63
    const int lc = (tid & 3) * 16;      // 0,16,32,48

    // load Q tile
    {
        const float* qrow = Q + (size_t)(n0 + lr) * DIM + base + lc;
        #pragma unroll
        for (int c = 0; c < 16; c += 4) {
            float4 v4 = *(const float4*)(qrow + c);
            Qs[lr * TPAD + lc + c + 0] = v4.x; Qs[lr * TPAD + lc + c + 1] = v4.y;
            Qs[lr * TPAD + lc + c + 2] = v4.z; Qs[lr * TPAD + lc + c + 3] = v4.w;
        }
    }

    float m[4], l[4], o[4][4] = {};
    #pragma unroll
    for (int i = 0; i < 4; ++i) { m[i] = -INFINITY; l[i] = 0.0f; }

    const float scale = 0.125f;  // 1/sqrt(64)

    for (int kv0 = 0; kv0 < N_TOK; kv0 += 64) {
        // load K tile
        {
            const float* krow = K + (size_t)(kv0 + lr) * DIM + base + lc;
            #pragma unroll
            for (int c = 0; c < 16; c += 4) {
                float4 v4 = *(const float4*)(krow + c);
                KVs[lr * TPAD + lc + c + 0] = v4.x; KVs[lr * TPAD + lc + c + 1] = v4.y;
                KVs[lr * TPAD + lc + c + 2] = v4.z; KVs[lr * TPAD + lc + c + 3] = v4.w;
            }
        }
        __syncthreads();

        // S = Q . K^T  (64x64x64)
        float s[4][4] = {};
        #pragma unroll 8
        for (int d = 0; d < HDIM; ++d) {
            float a[4], b[4];
            #pragma unroll
            for (int i = 0; i < 4; ++i) a[i] = Qs[(ty * 4 + i) * TPAD + d];
            #pragma unroll
            for (int j = 0; j < 4; ++j) b[j] = KVs[(tx * 4 + j) * TPAD + d];
            #pragma unroll
            for (int i = 0; i < 4; ++i)
                #pragma unroll
                for (int j = 0; j < 4; ++j)
                    s[i][j] = fmaf(a[i], b[j], s[i][j]);
        }

        // online softmax per row (rows owned by this thread: ty*4+i)
        #pragma unroll
        for (int i = 0; i < 4; ++i) {
            #pragma unroll
            for (int j = 0; j < 4; ++j) s[i][j] *= scale;

            float tm = fmaxf(fmaxf(s[i][0], s[i][1]), fmaxf(s[i][2], s[i][3]));
            #pragma unroll
            for (int msk = 8; msk >= 1; msk >>= 1)
                tm = fmaxf(tm, __shfl_xor_sync(0xffffffffu, tm, msk));

            float mn = fmaxf(m[i], tm);
            float f  = __expf(m[i] - mn);     // 0 on first tile (m=-inf)

            float sum = 0.0f;
            #pragma unroll
            for (int j = 0; j < 4; ++j) {
                s[i][j] = __expf(s[i][j] - mn);
                sum += s[i][j];
            }
            #pragma unroll
            for (int msk = 8; msk >= 1; msk >>= 1)
                sum += __shfl_xor_sync(0xffffffffu, sum, msk);

            l[i] = l[i] * f + sum;
            m[i] = mn;
            #pragma unroll
            for (int j = 0; j < 4; ++j) o[i][j] *= f;

            // stage P for the PV gemm
            #pragma unroll
            for (int j = 0; j < 4; ++j)
                Ps[(ty * 4 + i) * TPAD + tx * 4 + j] = s[i][j];
        }
        __syncthreads();   // K reads done, P visible

        // load V tile into KVs
        {
            const float* vrow = V + (size_t)(kv0 + lr) * DIM + base + lc;
            #pragma unroll
            for (int c = 0; c < 16; c += 4) {
                float4 v4 = *(const float4*)(vrow + c);
                KVs[lr * TPAD + lc + c + 0] = v4.x; KVs[lr * TPAD + lc + c + 1] = v4.y;
                KVs[lr * TPAD + lc + c + 2] = v4.z; KVs[lr * TPAD + lc + c + 3] = v4.w;
            }
        }
        __syncthreads();   // V ready

        // O += P . V  (64x64x64)
        #pragma unroll 8
        for (int kv = 0; kv < 64; ++kv) {
            float a[4], b[4];
            #pragma unroll
            for (int i = 0; i < 4; ++i) a[i] = Ps[(ty * 4 + i) * TPAD + kv];
            #pragma unroll
            for (int j = 0; j < 4; ++j) b[j] = KVs[kv * TPAD + tx * 4 + j];
            #pragma unroll
            for (int i = 0; i < 4; ++i)
                #pragma unroll
                for (int j = 0; j < 4; ++j)
                    o[i][j] = fmaf(a[i], b[j], o[i][j]);
        }
        __syncthreads();   // P/V consumed before next tile overwrites
    }

    // epilogue: normalize and write back in [N, 1024] layout
    #pragma unroll
    for (int i = 0; i < 4; ++i) {
        float inv_l = 1.0f / l[i];
        float* orow = O + (size_t)(n0 + ty * 4 + i) * DIM + base;
        #pragma unroll
        for (int j = 0; j < 4; ++j)
            orow[tx * 4 + j] = o[i][j] * inv_l;
    }
}

// ---------------------------------------------------------------------------
// Launch
// ---------------------------------------------------------------------------
extern "C" void kernel_launch(void* const* d_in, const int* in_sizes, int n_in,
                              void* d_out, int out_size)
{
    const float* x  = (const float*)d_in[0];
    const float* Wq = (const float*)d_in[1];
    const float* bq = (const float*)d_in[2];
    const float* Wk = (const float*)d_in[3];
    const float* bk = (const float*)d_in[4];
    const float* Wv = (const float*)d_in[5];
    const float* bv = (const float*)d_in[6];
    const float* Wo = (const float*)d_in[7];
    const float* bo = (const float*)d_in[8];
    float* out = (float*)d_out;

    float *q, *k, *v, *attn;
    cudaGetSymbolAddress((void**)&q,    g_q);
    cudaGetSymbolAddress((void**)&k,    g_k);
    cudaGetSymbolAddress((void**)&v,    g_v);
    cudaGetSymbolAddress((void**)&attn, g_attn);

    // opt-in to >48KB dynamic shared memory for the attention kernel
    // (deterministic, non-stream, non-allocating API call)
    cudaFuncSetAttribute(attn_kernel,
                         cudaFuncAttributeMaxDynamicSharedMemorySize,
                         ATTN_SMEM_BYTES);

    dim3 gthreads(16, 16);
    dim3 ggrid(DIM / 64, N_TOK / 64);   // (16, 64)

    gemm_bias_kernel<<<ggrid, gthreads>>>(x, Wq, bq, q);
    gemm_bias_kernel<<<ggrid, gthreads>>>(x, Wk, bk, k);
    gemm_bias_kernel<<<ggrid, gthreads>>>(x, Wv, bv, v);

    dim3 agrid(N_TOK / 64, NHEAD);      // (64, 16)
    attn_kernel<<<agrid, gthreads, ATTN_SMEM_BYTES>>>(q, k, v, attn);

    gemm_bias_kernel<<<ggrid, gthreads>>>(attn, Wo, bo, out);
}

// round 5
// speedup vs baseline: 4.2110x; 4.2110x over previous
#include <cuda_runtime.h>
#include <cuda_fp16.h>
#include <math.h>
#include <stdint.h>

#define N_TOK 4096
#define DIM   1024
#define NHEAD 16
#define HDIM  64

// ---------------------------------------------------------------------------
// Scratch (static device globals — no runtime allocation)
// ---------------------------------------------------------------------------
__device__ __half g_xh [N_TOK * DIM];
__device__ __half g_wqh[DIM * DIM];
__device__ __half g_wkh[DIM * DIM];
__device__ __half g_wvh[DIM * DIM];
__device__ __half g_woh[DIM * DIM];
__device__ __half g_qh [N_TOK * DIM];
__device__ __half g_kh [N_TOK * DIM];
__device__ __half g_vh [N_TOK * DIM];
__device__ __half g_vt [DIM * N_TOK];                      // V^T: [c][m]
__device__ __half g_s  [(size_t)NHEAD * N_TOK * N_TOK];    // scores/probs (512 MB)
__device__ __half g_ao [N_TOK * DIM];                      // attention output

// ---------------------------------------------------------------------------
// helpers
// ---------------------------------------------------------------------------
__device__ __forceinline__ uint32_t smem_u32(const void* p) {
    uint32_t a;
    asm("{ .reg .u64 t; cvta.to.shared.u64 t, %1; cvt.u32.u64 %0, t; }"
        : "=r"(a) : "l"(p));
    return a;
}

#define STS128(addr, v) \
    asm volatile("st.shared.v4.b32 [%0], {%1,%2,%3,%4};" \
                 :: "r"((uint32_t)(addr)), "r"((v).x), "r"((v).y), "r"((v).z), "r"((v).w) : "memory")

#define LDSM4(r0, r1, r2, r3, addr) \
    asm volatile("ldmatrix.sync.aligned.m8n8.x4.shared.b16 {%0,%1,%2,%3}, [%4];" \
                 : "=r"(r0), "=r"(r1), "=r"(r2), "=r"(r3) : "r"((uint32_t)(addr)))

#define MMA16816(c, a, b) \
    asm volatile("mma.sync.aligned.m16n8k16.row.col.f32.f16.f16.f32 " \
                 "{%0,%1,%2,%3}, {%4,%5,%6,%7}, {%8,%9}, {%0,%1,%2,%3};" \
                 : "+f"((c)[0]), "+f"((c)[1]), "+f"((c)[2]), "+f"((c)[3]) \
                 : "r"((a)[0]), "r"((a)[1]), "r"((a)[2]), "r"((a)[3]), \
                   "r"((b)[0]), "r"((b)[1]))

// ---------------------------------------------------------------------------
// fp32 -> fp16 convert
// ---------------------------------------------------------------------------
__global__ void cvt_f32_f16(const float* __restrict__ in, __half* __restrict__ out, int n2)
{
    int i = blockIdx.x * blockDim.x + threadIdx.x;
    if (i < n2) {
        float2 v = ((const float2*)in)[i];
        ((__half2*)out)[i] = __floats2half2_rn(v.x, v.y);
    }
}

// ---------------------------------------------------------------------------
// Transpose [4096][1024] fp16 -> [1024][4096] fp16
// ---------------------------------------------------------------------------
__global__ __launch_bounds__(256)
void transpose_kernel(const __half* __restrict__ in, __half* __restrict__ out)
{
    __shared__ __half tile[64][66];
    const int m0 = blockIdx.x * 64;
    const int c0 = blockIdx.y * 64;
    const int t = threadIdx.x;

    #pragma unroll
    for (int j = 0; j < 16; ++j) {
        int lin = j * 256 + t;
        int r = lin >> 6, c = lin & 63;
        tile[r][c] = in[(size_t)(m0 + r) * DIM + c0 + c];
    }
    __syncthreads();
    #pragma unroll
    for (int j = 0; j < 16; ++j) {
        int lin = j * 256 + t;
        int r = lin >> 6, c = lin & 63;
        out[(size_t)(c0 + r) * N_TOK + m0 + c] = tile[c][r];
    }
}

// ---------------------------------------------------------------------------
// Row softmax in place over fp16 rows of length 4096. One block per row.
// ---------------------------------------------------------------------------
__global__ __launch_bounds__(128)
void softmax_kernel(__half* __restrict__ S)
{
    __shared__ float red[4];
    const int t = threadIdx.x;
    const int wid = t >> 5, lane = t & 31;
    __half2* p2 = (__half2*)(S + (size_t)blockIdx.x * N_TOK);

    float2 v[16];
    float mx = -1e30f;
    #pragma unroll
    for (int j = 0; j < 16; ++j) {
        __half2 h = p2[t + j * 128];
        v[j] = __half22float2(h);
        mx = fmaxf(mx, fmaxf(v[j].x, v[j].y));
    }
    #pragma unroll
    for (int m = 16; m; m >>= 1) mx = fmaxf(mx, __shfl_xor_sync(0xffffffffu, mx, m));
    if (lane == 0) red[wid] = mx;
    __syncthreads();
    mx = fmaxf(fmaxf(red[0], red[1]), fmaxf(red[2], red[3]));
    __syncthreads();

    float s = 0.0f;
    #pragma unroll
    for (int j = 0; j < 16; ++j) {
        v[j].x = __expf(v[j].x - mx);
        v[j].y = __expf(v[j].y - mx);
        s += v[j].x + v[j].y;
    }
    #pragma unroll
    for (int m = 16; m; m >>= 1) s += __shfl_xor_sync(0xffffffffu, s, m);
    if (lane == 0) red[wid] = s;
    __syncthreads();
    s = red[0] + red[1] + red[2] + red[3];
    float inv = 1.0f / s;

    #pragma unroll
    for (int j = 0; j < 16; ++j)
        p2[t + j * 128] = __floats2half2_rn(v[j].x * inv, v[j].y * inv);
}

// ---------------------------------------------------------------------------
// Batched NT GEMM on mma.sync (m16n8k16, fp16 in, fp32 accum):
//   C[z][m][n] = alpha * sum_k A[z][m][k] * B[z][n][k]  (+ bias[n])
// Tile 128 x BN, BK=32, 8 warps (WM x WN), double-buffered padded smem.
// ---------------------------------------------------------------------------
template<int BN, int WM, int WN, int OUT_HALF>
__global__ __launch_bounds__(256)
void gemm_nt(const __half* __restrict__ A, const __half* __restrict__ B,
             const float* __restrict__ bias, void* __restrict__ C,
             int K, int lda, int ldb, int ldc,
             long long bsA, long long bsB, long long bsC, float alpha)
{
    constexpr int WTM = 128 / WM;         // warp tile rows (64 or 32)
    constexpr int WTN = BN / WN;          // warp tile cols (32)
    constexpr int MI  = WTM / 16;         // m16 frags per warp (4 or 2)
    constexpr int NI  = WTN / 8;          // n8 frags per warp (4)
    constexpr int ROWB = 40;              // halfs per smem row (32 data + 8 pad)
    constexpr int ABYTES = 128 * ROWB * 2;
    constexpr int BBYTES = BN * ROWB * 2;
    constexpr int BUF = ABYTES + BBYTES;
    constexpr int NBCH = BN * 4 / 256;    // B uint4 chunks per thread (1 or 2)

    __shared__ __half smem[2 * (128 + BN) * ROWB];

    const int tid  = threadIdx.x;
    const int warp = tid >> 5, lane = tid & 31;
    const int wm = warp % WM, wn = warp / WM;
    const int bm = blockIdx.y * 128;
    const int bn = blockIdx.x * BN;

    const __half* Ab = A + (size_t)blockIdx.z * bsA;
    const __half* Bb = B + (size_t)blockIdx.z * bsB;

    const uint32_t sbase = smem_u32(smem);

    // ldmatrix byte offsets within a buffer
    uint32_t aoff[MI][2], boff[NI / 2][2];
    #pragma unroll
    for (int mi = 0; mi < MI; ++mi)
        #pragma unroll
        for (int ks = 0; ks < 2; ++ks) {
            int row = wm * WTM + mi * 16 + (lane & 15);
            int col = ks * 16 + (lane >> 4) * 8;
            aoff[mi][ks] = (uint32_t)((row * ROWB + col) * 2);
        }
    #pragma unroll
    for (int nj = 0; nj < NI / 2; ++nj)
        #pragma unroll
        for (int ks = 0; ks < 2; ++ks) {
            int row = wn * WTN + nj * 16 + (lane & 7) + ((lane >> 4) << 3);
            int col = ks * 16 + ((lane >> 3) & 1) * 8;
            boff[nj][ks] = (uint32_t)(ABYTES + (row * ROWB + col) * 2);
        }

    float acc[MI][NI][4] = {};
    uint4 ra[2], rb[NBCH];

    auto LOADG = [&](int kt) {
        const int k0 = kt * 32;
        #pragma unroll
        for (int j = 0; j < 2; ++j) {
            int ch = j * 256 + tid;
            int r = ch >> 2, c = ch & 3;
            ra[j] = *(const uint4*)(Ab + (size_t)(bm + r) * lda + k0 + c * 8);
        }
        #pragma unroll
        for (int j = 0; j < NBCH; ++j) {
            int ch = j * 256 + tid;
            int r = ch >> 2, c = ch & 3;
            rb[j] = *(const uint4*)(Bb + (size_t)(bn + r) * ldb + k0 + c * 8);
        }
    };
    auto STORES = [&](int b) {
        uint32_t ab = sbase + b * BUF;
        #pragma unroll
        for (int j = 0; j < 2; ++j) {
            int ch = j * 256 + tid;
            int r = ch >> 2, c = ch & 3;
            STS128(ab + (r * ROWB + c * 8) * 2, ra[j]);
        }
        uint32_t bb = ab + ABYTES;
        #pragma unroll
        for (int j = 0; j < NBCH; ++j) {
            int ch = j * 256 + tid;
            int r = ch >> 2, c = ch & 3;
            STS128(bb + (r * ROWB + c * 8) * 2, rb[j]);
        }
    };
    auto COMPUTE = [&](int b) {
        uint32_t base = sbase + b * BUF;
        #pragma unroll
        for (int ks = 0; ks < 2; ++ks) {
            uint32_t af[MI][4], bf[NI][2];
            #pragma unroll
            for (int mi = 0; mi < MI; ++mi)
                LDSM4(af[mi][0], af[mi][1], af[mi][2], af[mi][3], base + aoff[mi][ks]);
            #pragma unroll
            for (int nj = 0; nj < NI / 2; ++nj) {
                uint32_t r0, r1, r2, r3;
                LDSM4(r0, r1, r2, r3, base + boff[nj][ks]);
                bf[nj * 2][0] = r0;  bf[nj * 2][1] = r1;
                bf[nj * 2 + 1][0] = r2;  bf[nj * 2 + 1][1] = r3;
            }
            #pragma unroll
            for (int mi = 0; mi < MI; ++mi)
                #pragma unroll
                for (int ni = 0; ni < NI; ++ni)
                    MMA16816(acc[mi][ni], af[mi], bf[ni]);
        }
    };

    LOADG(0);
    STORES(0);
    __syncthreads();

    const int KT = K / 32;
    for (int kt = 0; kt < KT; ++kt) {
        if (kt + 1 < KT) LOADG(kt + 1);
        COMPUTE(kt & 1);
        if (kt + 1 < KT) {
            STORES((kt + 1) & 1);
            __syncthreads();
        }
    }

    // epilogue
    const size_t cbz = (size_t)blockIdx.z * bsC;
    #pragma unroll
    for (int mi = 0; mi < MI; ++mi) {
        int row = bm + wm * WTM + mi * 16 + (lane >> 2);
        #pragma unroll
        for (int ni = 0; ni < NI; ++ni) {
            int col = bn + wn * WTN + ni * 8 + (lane & 3) * 2;
            float b0 = bias ? bias[col]     : 0.0f;
            float b1 = bias ? bias[col + 1] : 0.0f;
            float v0 = acc[mi][ni][0] * alpha + b0;
            float v1 = acc[mi][ni][1] * alpha + b1;
            float v2 = acc[mi][ni][2] * alpha + b0;
            float v3 = acc[mi][ni][3] * alpha + b1;
            if (OUT_HALF) {
                __half* Ch = (__half*)C;
                *(__half2*)(Ch + cbz + (size_t)row * ldc + col)       = __floats2half2_rn(v0, v1);
                *(__half2*)(Ch + cbz + (size_t)(row + 8) * ldc + col) = __floats2half2_rn(v2, v3);
            } else {
                float* Cf = (float*)C;
                *(float2*)(Cf + cbz + (size_t)row * ldc + col)        = make_float2(v0, v1);
                *(float2*)(Cf + cbz + (size_t)(row + 8) * ldc + col)  = make_float2(v2, v3);
            }
        }
    }
}

// ---------------------------------------------------------------------------
// Launch
// ---------------------------------------------------------------------------
extern "C" void kernel_launch(void* const* d_in, const int* in_sizes, int n_in,
                              void* d_out, int out_size)
{
    const float* x  = (const float*)d_in[0];
    const float* Wq = (const float*)d_in[1];
    const float* bq = (const float*)d_in[2];
    const float* Wk = (const float*)d_in[3];
    const float* bk = (const float*)d_in[4];
    const float* Wv = (const float*)d_in[5];
    const float* bv = (const float*)d_in[6];
    const float* Wo = (const float*)d_in[7];
    const float* bo = (const float*)d_in[8];
    float* out = (float*)d_out;

    __half *xh, *wqh, *wkh, *wvh, *woh, *qh, *kh, *vh, *vt, *S, *ao;
    cudaGetSymbolAddress((void**)&xh,  g_xh);
    cudaGetSymbolAddress((void**)&wqh, g_wqh);
    cudaGetSymbolAddress((void**)&wkh, g_wkh);
    cudaGetSymbolAddress((void**)&wvh, g_wvh);
    cudaGetSymbolAddress((void**)&woh, g_woh);
    cudaGetSymbolAddress((void**)&qh,  g_qh);
    cudaGetSymbolAddress((void**)&kh,  g_kh);
    cudaGetSymbolAddress((void**)&vh,  g_vh);
    cudaGetSymbolAddress((void**)&vt,  g_vt);
    cudaGetSymbolAddress((void**)&S,   g_s);
    cudaGetSymbolAddress((void**)&ao,  g_ao);

    // convert inputs to fp16
    {
        int n2 = (N_TOK * DIM) / 2;
        cvt_f32_f16<<<(n2 + 255) / 256, 256>>>(x, xh, n2);
        int w2 = (DIM * DIM) / 2;
        cvt_f32_f16<<<(w2 + 255) / 256, 256>>>(Wq, wqh, w2);
        cvt_f32_f16<<<(w2 + 255) / 256, 256>>>(Wk, wkh, w2);
        cvt_f32_f16<<<(w2 + 255) / 256, 256>>>(Wv, wvh, w2);
        cvt_f32_f16<<<(w2 + 255) / 256, 256>>>(Wo, woh, w2);
    }

    dim3 pgrid(DIM / 128, N_TOK / 128, 1);      // (8, 32)

    // Q/K/V projections (fp16 out)
    gemm_nt<128, 2, 4, 1><<<pgrid, 256>>>(xh, wqh, bq, qh, DIM, DIM, DIM, DIM, 0, 0, 0, 1.0f);
    gemm_nt<128, 2, 4, 1><<<pgrid, 256>>>(xh, wkh, bk, kh, DIM, DIM, DIM, DIM, 0, 0, 0, 1.0f);
    gemm_nt<128, 2, 4, 1><<<pgrid, 256>>>(xh, wvh, bv, vh, DIM, DIM, DIM, DIM, 0, 0, 0, 1.0f);

    // V -> V^T
    transpose_kernel<<<dim3(N_TOK / 64, DIM / 64), 256>>>(vh, vt);

    // scores: S[h] = 0.125 * Q_h @ K_h^T  (fp16, [4096][4096] per head)
    {
        dim3 grid(N_TOK / 128, N_TOK / 128, NHEAD);   // (32, 32, 16)
        gemm_nt<128, 2, 4, 1><<<grid, 256>>>(
            qh, kh, nullptr, S, HDIM, DIM, DIM, N_TOK,
            HDIM, HDIM, (long long)N_TOK * N_TOK, 0.125f);
    }

    // softmax over all rows
    softmax_kernel<<<NHEAD * N_TOK, 128>>>(S);

    // PV: AO[:, h*64:(h+1)*64] = P[h] @ V_h   (BN=64 tile, K=4096)
    {
        dim3 grid(1, N_TOK / 128, NHEAD);             // (1, 32, 16)
        gemm_nt<64, 4, 2, 1><<<grid, 256>>>(
            S, vt, nullptr, ao, N_TOK, N_TOK, N_TOK, DIM,
            (long long)N_TOK * N_TOK, (long long)HDIM * N_TOK, HDIM, 1.0f);
    }

    // output projection (fp32 out)
    gemm_nt<128, 2, 4, 0><<<pgrid, 256>>>(ao, woh, bo, out, DIM, DIM, DIM, DIM, 0, 0, 0, 1.0f);
}

// round 6
// speedup vs baseline: 7.4163x; 1.7612x over previous
#include <cuda_runtime.h>
#include <cuda_fp16.h>
#include <math.h>
#include <stdint.h>

#define N_TOK 4096
#define DIM   1024
#define NHEAD 16
#define HDIM  64

// ---------------------------------------------------------------------------
// Scratch (static device globals — no runtime allocation)
// ---------------------------------------------------------------------------
__device__ __half g_xh [N_TOK * DIM];
__device__ __half g_wqh[DIM * DIM];
__device__ __half g_wkh[DIM * DIM];
__device__ __half g_wvh[DIM * DIM];
__device__ __half g_woh[DIM * DIM];
__device__ __half g_qh [N_TOK * DIM];
__device__ __half g_kh [N_TOK * DIM];
__device__ __half g_vh [N_TOK * DIM];
__device__ __half g_vt [DIM * N_TOK];   // V^T: [head_col][token]
__device__ __half g_ao [N_TOK * DIM];   // attention output

// ---------------------------------------------------------------------------
// helpers
// ---------------------------------------------------------------------------
__device__ __forceinline__ uint32_t smem_u32(const void* p) {
    uint32_t a;
    asm("{ .reg .u64 t; cvta.to.shared.u64 t, %1; cvt.u32.u64 %0, t; }"
        : "=r"(a) : "l"(p));
    return a;
}

__device__ __forceinline__ uint32_t h2_u32(__half2 h) {
    return *(uint32_t*)&h;
}

#define STS128(addr, v) \
    asm volatile("st.shared.v4.b32 [%0], {%1,%2,%3,%4};" \
                 :: "r"((uint32_t)(addr)), "r"((v).x), "r"((v).y), "r"((v).z), "r"((v).w) : "memory")

#define LDSM4(r0, r1, r2, r3, addr) \
    asm volatile("ldmatrix.sync.aligned.m8n8.x4.shared.b16 {%0,%1,%2,%3}, [%4];" \
                 : "=r"(r0), "=r"(r1), "=r"(r2), "=r"(r3) : "r"((uint32_t)(addr)))

#define MMA16816(c, a, b) \
    asm volatile("mma.sync.aligned.m16n8k16.row.col.f32.f16.f16.f32 " \
                 "{%0,%1,%2,%3}, {%4,%5,%6,%7}, {%8,%9}, {%0,%1,%2,%3};" \
                 : "+f"((c)[0]), "+f"((c)[1]), "+f"((c)[2]), "+f"((c)[3]) \
                 : "r"((a)[0]), "r"((a)[1]), "r"((a)[2]), "r"((a)[3]), \
                   "r"((b)[0]), "r"((b)[1]))

// ---------------------------------------------------------------------------
// fp32 -> fp16 convert
// ---------------------------------------------------------------------------
__global__ void cvt_f32_f16(const float* __restrict__ in, __half* __restrict__ out, int n2)
{
    int i = blockIdx.x * blockDim.x + threadIdx.x;
    if (i < n2) {
        float2 v = ((const float2*)in)[i];
        ((__half2*)out)[i] = __floats2half2_rn(v.x, v.y);
    }
}

// ---------------------------------------------------------------------------
// Transpose [4096][1024] fp16 -> [1024][4096] fp16
// ---------------------------------------------------------------------------
__global__ __launch_bounds__(256)
void transpose_kernel(const __half* __restrict__ in, __half* __restrict__ out)
{
    __shared__ __half tile[64][66];
    const int m0 = blockIdx.x * 64;
    const int c0 = blockIdx.y * 64;
    const int t = threadIdx.x;

    #pragma unroll
    for (int j = 0; j < 16; ++j) {
        int lin = j * 256 + t;
        int r = lin >> 6, c = lin & 63;
        tile[r][c] = in[(size_t)(m0 + r) * DIM + c0 + c];
    }
    __syncthreads();
    #pragma unroll
    for (int j = 0; j < 16; ++j) {
        int lin = j * 256 + t;
        int r = lin >> 6, c = lin & 63;
        out[(size_t)(c0 + r) * N_TOK + m0 + c] = tile[c][r];
    }
}

// ---------------------------------------------------------------------------
// Batched NT GEMM on mma.sync (m16n8k16, fp16 in, fp32 accum)
// Tile 128 x BN, BK=32, 8 warps, double-buffered padded smem.
// ---------------------------------------------------------------------------
template<int BN, int WM, int WN, int OUT_HALF>
__global__ __launch_bounds__(256)
void gemm_nt(const __half* __restrict__ A, const __half* __restrict__ B,
             const float* __restrict__ bias, void* __restrict__ C,
             int K, int lda, int ldb, int ldc,
             long long bsA, long long bsB, long long bsC, float alpha)
{
    constexpr int WTM = 128 / WM;
    constexpr int WTN = BN / WN;
    constexpr int MI  = WTM / 16;
    constexpr int NI  = WTN / 8;
    constexpr int ROWB = 40;
    constexpr int ABYTES = 128 * ROWB * 2;
    constexpr int BBYTES = BN * ROWB * 2;
    constexpr int BUF = ABYTES + BBYTES;
    constexpr int NBCH = BN * 4 / 256;

    __shared__ __half smem[2 * (128 + BN) * ROWB];

    const int tid  = threadIdx.x;
    const int warp = tid >> 5, lane = tid & 31;
    const int wm = warp % WM, wn = warp / WM;
    const int bm = blockIdx.y * 128;
    const int bn = blockIdx.x * BN;

    const __half* Ab = A + (size_t)blockIdx.z * bsA;
    const __half* Bb = B + (size_t)blockIdx.z * bsB;

    const uint32_t sbase = smem_u32(smem);

    uint32_t aoff[MI][2], boff[NI / 2][2];
    #pragma unroll
    for (int mi = 0; mi < MI; ++mi)
        #pragma unroll
        for (int ks = 0; ks < 2; ++ks) {
            int row = wm * WTM + mi * 16 + (lane & 15);
            int col = ks * 16 + (lane >> 4) * 8;
            aoff[mi][ks] = (uint32_t)((row * ROWB + col) * 2);
        }
    #pragma unroll
    for (int nj = 0; nj < NI / 2; ++nj)
        #pragma unroll
        for (int ks = 0; ks < 2; ++ks) {
            int row = wn * WTN + nj * 16 + (lane & 7) + ((lane >> 4) << 3);
            int col = ks * 16 + ((lane >> 3) & 1) * 8;
            boff[nj][ks] = (uint32_t)(ABYTES + (row * ROWB + col) * 2);
        }

    float acc[MI][NI][4] = {};
    uint4 ra[2], rb[NBCH];

    auto LOADG = [&](int kt) {
        const int k0 = kt * 32;
        #pragma unroll
        for (int j = 0; j < 2; ++j) {
            int ch = j * 256 + tid;
            int r = ch >> 2, c = ch & 3;
            ra[j] = *(const uint4*)(Ab + (size_t)(bm + r) * lda + k0 + c * 8);
        }
        #pragma unroll
        for (int j = 0; j < NBCH; ++j) {
            int ch = j * 256 + tid;
            int r = ch >> 2, c = ch & 3;
            rb[j] = *(const uint4*)(Bb + (size_t)(bn + r) * ldb + k0 + c * 8);
        }
    };
    auto STORES = [&](int b) {
        uint32_t ab = sbase + b * BUF;
        #pragma unroll
        for (int j = 0; j < 2; ++j) {
            int ch = j * 256 + tid;
            int r = ch >> 2, c = ch & 3;
            STS128(ab + (r * ROWB + c * 8) * 2, ra[j]);
        }
        uint32_t bb = ab + ABYTES;
        #pragma unroll
        for (int j = 0; j < NBCH; ++j) {
            int ch = j * 256 + tid;
            int r = ch >> 2, c = ch & 3;
            STS128(bb + (r * ROWB + c * 8) * 2, rb[j]);
        }
    };
    auto COMPUTE = [&](int b) {
        uint32_t base = sbase + b * BUF;
        #pragma unroll
        for (int ks = 0; ks < 2; ++ks) {
            uint32_t af[MI][4], bf[NI][2];
            #pragma unroll
            for (int mi = 0; mi < MI; ++mi)
                LDSM4(af[mi][0], af[mi][1], af[mi][2], af[mi][3], base + aoff[mi][ks]);
            #pragma unroll
            for (int nj = 0; nj < NI / 2; ++nj) {
                uint32_t r0, r1, r2, r3;
                LDSM4(r0, r1, r2, r3, base + boff[nj][ks]);
                bf[nj * 2][0] = r0;  bf[nj * 2][1] = r1;
                bf[nj * 2 + 1][0] = r2;  bf[nj * 2 + 1][1] = r3;
            }
            #pragma unroll
            for (int mi = 0; mi < MI; ++mi)
                #pragma unroll
                for (int ni = 0; ni < NI; ++ni)
                    MMA16816(acc[mi][ni], af[mi], bf[ni]);
        }
    };

    LOADG(0);
    STORES(0);
    __syncthreads();

    const int KT = K / 32;
    for (int kt = 0; kt < KT; ++kt) {
        if (kt + 1 < KT) LOADG(kt + 1);
        COMPUTE(kt & 1);
        if (kt + 1 < KT) {
            STORES((kt + 1) & 1);
            __syncthreads();
        }
    }

    const size_t cbz = (size_t)blockIdx.z * bsC;
    #pragma unroll
    for (int mi = 0; mi < MI; ++mi) {
        int row = bm + wm * WTM + mi * 16 + (lane >> 2);
        #pragma unroll
        for (int ni = 0; ni < NI; ++ni) {
            int col = bn + wn * WTN + ni * 8 + (lane & 3) * 2;
            float b0 = bias ? bias[col]     : 0.0f;
            float b1 = bias ? bias[col + 1] : 0.0f;
            float v0 = acc[mi][ni][0] * alpha + b0;
            float v1 = acc[mi][ni][1] * alpha + b1;
            float v2 = acc[mi][ni][2] * alpha + b0;
            float v3 = acc[mi][ni][3] * alpha + b1;
            if (OUT_HALF) {
                __half* Ch = (__half*)C;
                *(__half2*)(Ch + cbz + (size_t)row * ldc + col)       = __floats2half2_rn(v0, v1);
                *(__half2*)(Ch + cbz + (size_t)(row + 8) * ldc + col) = __floats2half2_rn(v2, v3);
            } else {
                float* Cf = (float*)C;
                *(float2*)(Cf + cbz + (size_t)row * ldc + col)        = make_float2(v0, v1);
                *(float2*)(Cf + cbz + (size_t)(row + 8) * ldc + col)  = make_float2(v2, v3);
            }
        }
    }
}

// ---------------------------------------------------------------------------
// Fused flash attention on mma.sync.
// grid = (N_TOK/128, NHEAD); 256 threads = 8 warps, warp w owns q rows w*16..+15.
// S kept in fp32 regs; P converted in-register to mma A-frags; O accum fp32.
// K tile 128x64 in sK; V^T tile 64x128 in sV.
// ---------------------------------------------------------------------------
__global__ __launch_bounds__(256)
void flash_kernel(const __half* __restrict__ Q, const __half* __restrict__ K,
                  const __half* __restrict__ VT, __half* __restrict__ O)
{
    __shared__ __half sK[128 * 72];
    __shared__ __half sV[64 * 136];

    const int tid  = threadIdx.x;
    const int warp = tid >> 5, lane = tid & 31;
    const int q0   = blockIdx.x * 128;
    const int head = blockIdx.y;

    const __half* Qp = Q  + (size_t)q0 * DIM + head * HDIM;
    const __half* Kp = K  + head * HDIM;
    const __half* Vp = VT + (size_t)head * HDIM * N_TOK;

    const uint32_t kb = smem_u32(sK);
    const uint32_t vb = smem_u32(sV);

    // ---- stage Q tile (pre-scaled by 1/sqrt(64)=0.125, exact in fp16) ----
    {
        const __half2 sc = __half2half2(__float2half(0.125f));
        #pragma unroll
        for (int j = 0; j < 4; ++j) {
            int ch = j * 256 + tid;          // 0..1023
            int r = ch >> 3, c = ch & 7;
            uint4 u = *(const uint4*)(Qp + (size_t)r * DIM + c * 8);
            __half2* h = (__half2*)&u;
            h[0] = __hmul2(h[0], sc); h[1] = __hmul2(h[1], sc);
            h[2] = __hmul2(h[2], sc); h[3] = __hmul2(h[3], sc);
            STS128(kb + (r * 72 + c * 8) * 2, u);
        }
    }
    __syncthreads();

    // Q A-fragments (ks = 0..3 covers HDIM=64)
    uint32_t qf[4][4];
    #pragma unroll
    for (int ks = 0; ks < 4; ++ks) {
        int row = warp * 16 + (lane & 15);
        int col = ks * 16 + (lane >> 4) * 8;
        LDSM4(qf[ks][0], qf[ks][1], qf[ks][2], qf[ks][3], kb + (row * 72 + col) * 2);
    }
    __syncthreads();   // all warps done reading Q before K overwrites sK

    float m0 = -1e30f, m1 = -1e30f, l0 = 0.0f, l1 = 0.0f;
    float oacc[8][4] = {};
    uint4 rk[4], rv[4];

    auto LOADK = [&](int t) {
        const int kv0 = t * 128;
        #pragma unroll
        for (int j = 0; j < 4; ++j) {
            int ch = j * 256 + tid;
            int r = ch >> 3, c = ch & 7;
            rk[j] = *(const uint4*)(Kp + (size_t)(kv0 + r) * DIM + c * 8);
        }
    };
    auto LOADV = [&](int t) {
        const int kv0 = t * 128;
        #pragma unroll
        for (int j = 0; j < 4; ++j) {
            int ch = j * 256 + tid;
            int r = ch >> 4, c = ch & 15;
            rv[j] = *(const uint4*)(Vp + (size_t)r * N_TOK + kv0 + c * 8);
        }
    };
    auto STOREKV = [&]() {
        #pragma unroll
        for (int j = 0; j < 4; ++j) {
            int ch = j * 256 + tid;
            int r = ch >> 3, c = ch & 7;
            STS128(kb + (r * 72 + c * 8) * 2, rk[j]);
        }
        #pragma unroll
        for (int j = 0; j < 4; ++j) {
            int ch = j * 256 + tid;
            int r = ch >> 4, c = ch & 15;
            STS128(vb + (r * 136 + c * 8) * 2, rv[j]);
        }
    };

    LOADK(0); LOADV(0); STOREKV();
    __syncthreads();

    const int NT = N_TOK / 128;
    for (int t = 0; t < NT; ++t) {
        if (t + 1 < NT) LOADK(t + 1);     // prefetch next K during S compute

        // ---- S = (Q*scale) . K^T : 16 x 128 per warp, fp32 acc ----
        float s[16][4] = {};
        #pragma unroll
        for (int ks = 0; ks < 4; ++ks) {
            uint32_t bf[16][2];
            #pragma unroll
            for (int nj = 0; nj < 8; ++nj) {
                int row = nj * 16 + (lane & 7) + ((lane >> 4) << 3);
                int col = ks * 16 + ((lane >> 3) & 1) * 8;
                uint32_t r0, r1, r2, r3;
                LDSM4(r0, r1, r2, r3, kb + (row * 72 + col) * 2);
                bf[nj * 2][0] = r0;  bf[nj * 2][1] = r1;
                bf[nj * 2 + 1][0] = r2;  bf[nj * 2 + 1][1] = r3;
            }
            #pragma unroll
            for (int ni = 0; ni < 16; ++ni)
                MMA16816(s[ni], qf[ks], bf[ni]);
        }

        if (t + 1 < NT) LOADV(t + 1);     // prefetch next V during softmax/PV

        // ---- online softmax; rows r=lane>>2 (c0,c1) and r+8 (c2,c3) ----
        float rm0 = -1e30f, rm1 = -1e30f;
        #pragma unroll
        for (int ni = 0; ni < 16; ++ni) {
            rm0 = fmaxf(rm0, fmaxf(s[ni][0], s[ni][1]));
            rm1 = fmaxf(rm1, fmaxf(s[ni][2], s[ni][3]));
        }
        rm0 = fmaxf(rm0, __shfl_xor_sync(0xffffffffu, rm0, 1));
        rm0 = fmaxf(rm0, __shfl_xor_sync(0xffffffffu, rm0, 2));
        rm1 = fmaxf(rm1, __shfl_xor_sync(0xffffffffu, rm1, 1));
        rm1 = fmaxf(rm1, __shfl_xor_sync(0xffffffffu, rm1, 2));

        float mn0 = fmaxf(m0, rm0), mn1 = fmaxf(m1, rm1);
        float sc0 = __expf(m0 - mn0), sc1 = __expf(m1 - mn1);
        m0 = mn0; m1 = mn1;

        // exponentiate + pack P directly into A-fragment layout
        uint32_t pf[8][4];
        float sum0 = 0.0f, sum1 = 0.0f;
        #pragma unroll
        for (int ni = 0; ni < 16; ++ni) {
            float e0 = __expf(s[ni][0] - mn0);
            float e1 = __expf(s[ni][1] - mn0);
            float e2 = __expf(s[ni][2] - mn1);
            float e3 = __expf(s[ni][3] - mn1);
            sum0 += e0 + e1; sum1 += e2 + e3;
            uint32_t h01 = h2_u32(__floats2half2_rn(e0, e1));
            uint32_t h23 = h2_u32(__floats2half2_rn(e2, e3));
            int ks2 = ni >> 1;
            if ((ni & 1) == 0) { pf[ks2][0] = h01; pf[ks2][1] = h23; }
            else               { pf[ks2][2] = h01; pf[ks2][3] = h23; }
        }
        sum0 += __shfl_xor_sync(0xffffffffu, sum0, 1);
        sum0 += __shfl_xor_sync(0xffffffffu, sum0, 2);
        sum1 += __shfl_xor_sync(0xffffffffu, sum1, 1);
        sum1 += __shfl_xor_sync(0xffffffffu, sum1, 2);
        l0 = l0 * sc0 + sum0;
        l1 = l1 * sc1 + sum1;

        #pragma unroll
        for (int ni = 0; ni < 8; ++ni) {
            oacc[ni][0] *= sc0; oacc[ni][1] *= sc0;
            oacc[ni][2] *= sc1; oacc[ni][3] *= sc1;
        }

        // ---- O += P . V : k = 128 kv positions (8 ksteps), n = 64 head cols ----
        #pragma unroll
        for (int ks = 0; ks < 8; ++ks) {
            uint32_t vf[8][2];
            #pragma unroll
            for (int nj = 0; nj < 4; ++nj) {
                int row = nj * 16 + (lane & 7) + ((lane >> 4) << 3);
                int col = ks * 16 + ((lane >> 3) & 1) * 8;
                uint32_t r0, r1, r2, r3;
                LDSM4(r0, r1, r2, r3, vb + (row * 136 + col) * 2);
                vf[nj * 2][0] = r0;  vf[nj * 2][1] = r1;
                vf[nj * 2 + 1][0] = r2;  vf[nj * 2 + 1][1] = r3;
            }
            #pragma unroll
            for (int ni = 0; ni < 8; ++ni)
                MMA16816(oacc[ni], pf[ks], vf[ni]);
        }

        __syncthreads();                  // smem reads done
        if (t + 1 < NT) {
            STOREKV();
            __syncthreads();              // next tiles visible
        }
    }

    // ---- epilogue: O/l, write fp16 ----
    float inv0 = 1.0f / l0, inv1 = 1.0f / l1;
    int row = q0 + warp * 16 + (lane >> 2);
    #pragma unroll
    for (int ni = 0; ni < 8; ++ni) {
        int col = head * HDIM + ni * 8 + (lane & 3) * 2;
        *(__half2*)(O + (size_t)row * DIM + col) =
            __floats2half2_rn(oacc[ni][0] * inv0, oacc[ni][1] * inv0);
        *(__half2*)(O + (size_t)(row + 8) * DIM + col) =
            __floats2half2_rn(oacc[ni][2] * inv1, oacc[ni][3] * inv1);
    }
}

// ---------------------------------------------------------------------------
// Launch
// ---------------------------------------------------------------------------
extern "C" void kernel_launch(void* const* d_in, const int* in_sizes, int n_in,
                              void* d_out, int out_size)
{
    const float* x  = (const float*)d_in[0];
    const float* Wq = (const float*)d_in[1];
    const float* bq = (const float*)d_in[2];
    const float* Wk = (const float*)d_in[3];
    const float* bk = (const float*)d_in[4];
    const float* Wv = (const float*)d_in[5];
    const float* bv = (const float*)d_in[6];
    const float* Wo = (const float*)d_in[7];
    const float* bo = (const float*)d_in[8];
    float* out = (float*)d_out;

    __half *xh, *wqh, *wkh, *wvh, *woh, *qh, *kh, *vh, *vt, *ao;
    cudaGetSymbolAddress((void**)&xh,  g_xh);
    cudaGetSymbolAddress((void**)&wqh, g_wqh);
    cudaGetSymbolAddress((void**)&wkh, g_wkh);
    cudaGetSymbolAddress((void**)&wvh, g_wvh);
    cudaGetSymbolAddress((void**)&woh, g_woh);
    cudaGetSymbolAddress((void**)&qh,  g_qh);
    cudaGetSymbolAddress((void**)&kh,  g_kh);
    cudaGetSymbolAddress((void**)&vh,  g_vh);
    cudaGetSymbolAddress((void**)&vt,  g_vt);
    cudaGetSymbolAddress((void**)&ao,  g_ao);

    // convert inputs to fp16
    {
        int n2 = (N_TOK * DIM) / 2;
        cvt_f32_f16<<<(n2 + 255) / 256, 256>>>(x, xh, n2);
        int w2 = (DIM * DIM) / 2;
        cvt_f32_f16<<<(w2 + 255) / 256, 256>>>(Wq, wqh, w2);
        cvt_f32_f16<<<(w2 + 255) / 256, 256>>>(Wk, wkh, w2);
        cvt_f32_f16<<<(w2 + 255) / 256, 256>>>(Wv, wvh, w2);
        cvt_f32_f16<<<(w2 + 255) / 256, 256>>>(Wo, woh, w2);
    }

    dim3 pgrid(DIM / 128, N_TOK / 128, 1);      // (8, 32)

    // Q/K/V projections (fp16 out)
    gemm_nt<128, 2, 4, 1><<<pgrid, 256>>>(xh, wqh, bq, qh, DIM, DIM, DIM, DIM, 0, 0, 0, 1.0f);
    gemm_nt<128, 2, 4, 1><<<pgrid, 256>>>(xh, wkh, bk, kh, DIM, DIM, DIM, DIM, 0, 0, 0, 1.0f);
    gemm_nt<128, 2, 4, 1><<<pgrid, 256>>>(xh, wvh, bv, vh, DIM, DIM, DIM, DIM, 0, 0, 0, 1.0f);

    // V -> V^T
    transpose_kernel<<<dim3(N_TOK / 64, DIM / 64), 256>>>(vh, vt);

    // fused attention (scores + softmax + PV)
    flash_kernel<<<dim3(N_TOK / 128, NHEAD), 256>>>(qh, kh, vt, ao);

    // output projection (fp32 out)
    gemm_nt<128, 2, 4, 0><<<pgrid, 256>>>(ao, woh, bo, out, DIM, DIM, DIM, DIM, 0, 0, 0, 1.0f);
}